// round 2
// baseline (speedup 1.0000x reference)
#include <cuda_runtime.h>
#include <cuda_fp16.h>
#include <cstdint>

// ============================================================================
// Problem geometry
// ============================================================================
#define TOKENS 8192
#define D_IN   4096
#define D_OUT  4096

// GEMM tiling
#define BM 128
#define BN 128
#define BK 64
#define STAGES 4
#define NIT (D_IN / BK)          // 64 k-iterations

#define ASTAGE_BYTES (BM * BK * 2)          // 16384
#define BSTAGE_BYTES (BN * BK * 2)          // 16384
#define STAGE_BYTES  (ASTAGE_BYTES + BSTAGE_BYTES)   // 32768
#define SMEM_TOTAL   (STAGES * STAGE_BYTES)          // 131072

// fp16 staging buffers (device globals: no allocation allowed anywhere)
__device__ __align__(1024) __half g_xh[(size_t)TOKENS * D_IN];
__device__ __align__(1024) __half g_wh[(size_t)D_OUT * D_IN];

// ============================================================================
// PTX helpers (base sm_100 only: cp.async + ldmatrix + mma.sync)
// ============================================================================
__device__ __forceinline__ uint32_t smem_to_u32(const void* p) {
    uint32_t a;
    asm("{ .reg .u64 t; cvta.to.shared.u64 t, %1; cvt.u32.u64 %0, t; }"
        : "=r"(a) : "l"(p));
    return a;
}

__device__ __forceinline__ void cp_async16(uint32_t smem, const void* gmem) {
    asm volatile("cp.async.cg.shared.global [%0], [%1], 16;"
                 :: "r"(smem), "l"(gmem) : "memory");
}
#define CP_COMMIT() asm volatile("cp.async.commit_group;" ::: "memory")
#define CP_WAIT(N)  asm volatile("cp.async.wait_group %0;" :: "n"(N) : "memory")

__device__ __forceinline__ void ldsm_x4(uint32_t* r, uint32_t addr) {
    asm volatile("ldmatrix.sync.aligned.m8n8.x4.shared.b16 {%0,%1,%2,%3}, [%4];"
                 : "=r"(r[0]), "=r"(r[1]), "=r"(r[2]), "=r"(r[3]) : "r"(addr));
}
__device__ __forceinline__ void ldsm_x2(uint32_t* r, uint32_t addr) {
    asm volatile("ldmatrix.sync.aligned.m8n8.x2.shared.b16 {%0,%1}, [%2];"
                 : "=r"(r[0]), "=r"(r[1]) : "r"(addr));
}

__device__ __forceinline__ void mma16816(float* c, const uint32_t* a,
                                         const uint32_t* b) {
    asm volatile(
        "mma.sync.aligned.m16n8k16.row.col.f32.f16.f16.f32 "
        "{%0,%1,%2,%3}, {%4,%5,%6,%7}, {%8,%9}, {%0,%1,%2,%3};"
        : "+f"(c[0]), "+f"(c[1]), "+f"(c[2]), "+f"(c[3])
        : "r"(a[0]), "r"(a[1]), "r"(a[2]), "r"(a[3]), "r"(b[0]), "r"(b[1]));
}

// ============================================================================
// Conversion kernels: fp32 -> fp16 (x), int32 -> fp16 (weight, exact)
// ============================================================================
__global__ void __launch_bounds__(256) cvt_x_kernel(const float4* __restrict__ x,
                                                    __half2* __restrict__ o, int n4) {
    int i = blockIdx.x * blockDim.x + threadIdx.x;
    if (i < n4) {
        float4 v = x[i];
        o[2 * i + 0] = __floats2half2_rn(v.x, v.y);
        o[2 * i + 1] = __floats2half2_rn(v.z, v.w);
    }
}

__global__ void __launch_bounds__(256) cvt_w_kernel(const int4* __restrict__ w,
                                                    __half2* __restrict__ o, int n4) {
    int i = blockIdx.x * blockDim.x + threadIdx.x;
    if (i < n4) {
        int4 v = w[i];
        o[2 * i + 0] = __halves2half2(__int2half_rn(v.x), __int2half_rn(v.y));
        o[2 * i + 1] = __halves2half2(__int2half_rn(v.z), __int2half_rn(v.w));
    }
}

// ============================================================================
// GEMM: out[m,n] = scales[n] * sum_k xh[m,k] * wh[n,k] + bias[n]
//   A = xh [TOKENS, D_IN] K-major,  B = wh [D_OUT, D_IN] K-major  (TN GEMM)
//   128x128x64 tiles, 4-stage cp.async pipeline, 8 warps (2x4), warp tile 64x32
//   Smem layout: 16B chunks, chunk c of row r stored at (c ^ (r & 7))
// ============================================================================
__global__ void __launch_bounds__(256, 1) gemm_kernel(
    const __half* __restrict__ A,
    const __half* __restrict__ B,
    const float* __restrict__ scales,
    const float* __restrict__ bias,
    float* __restrict__ out) {
    extern __shared__ char smem[];
    const uint32_t sb = smem_to_u32(smem);
    const int tid = threadIdx.x;
    const int wid = tid >> 5;
    const int l = tid & 31;

    const int m0 = blockIdx.y * BM;
    const int n0 = blockIdx.x * BN;
    const int wm0 = (wid >> 2) * 64;     // warp row offset in tile
    const int wn0 = (wid & 3) * 32;      // warp col offset in tile

    // ---- stage loader: 1024 16B chunks for A and for B, swizzled ----
    auto load_stage = [&](int it, int st) {
        const int k0 = it * BK;
        const uint32_t sa = sb + st * STAGE_BYTES;
        const uint32_t sB = sa + ASTAGE_BYTES;
#pragma unroll
        for (int j = 0; j < 4; j++) {
            int q = tid + j * 256;
            int r = q >> 3, c = q & 7;
            uint32_t soff = (uint32_t)(r * 128 + ((c ^ (r & 7)) << 4));
            cp_async16(sa + soff, A + (size_t)(m0 + r) * D_IN + k0 + c * 8);
        }
#pragma unroll
        for (int j = 0; j < 4; j++) {
            int q = tid + j * 256;
            int r = q >> 3, c = q & 7;
            uint32_t soff = (uint32_t)(r * 128 + ((c ^ (r & 7)) << 4));
            cp_async16(sB + soff, B + (size_t)(n0 + r) * D_IN + k0 + c * 8);
        }
        CP_COMMIT();
    };

    // ---- prologue: fill STAGES-1 stages ----
#pragma unroll
    for (int s = 0; s < STAGES - 1; s++) load_stage(s, s);

    float acc[4][4][4];
#pragma unroll
    for (int mt = 0; mt < 4; mt++)
#pragma unroll
        for (int nt = 0; nt < 4; nt++)
#pragma unroll
            for (int q = 0; q < 4; q++) acc[mt][nt][q] = 0.0f;

    // ldmatrix lane addressing (swizzle xor reduces to l&7 since all row
    // offsets are multiples of 8)
    const uint32_t a_lane_row = (uint32_t)((wm0 + (l & 15)) * 128);
    const uint32_t b_lane_row = (uint32_t)((wn0 + (l & 7)) * 128);
    const int a_chunk_hi = (l >> 4);        // 0/1 -> k chunk within k16
    const int b_chunk_hi = (l >> 3) & 1;
    const int sw = l & 7;

    // ---- mainloop ----
    for (int it = 0; it < NIT; it++) {
        CP_WAIT(STAGES - 2);
        __syncthreads();

        // keep one commit per iteration so wait_group(STAGES-2) always
        // guarantees stage `it` is resident (no tail underflow)
        if (it + STAGES - 1 < NIT) {
            load_stage(it + STAGES - 1, (it + STAGES - 1) % STAGES);
        } else {
            CP_COMMIT();
        }

        const uint32_t sa = sb + (it % STAGES) * STAGE_BYTES;
        const uint32_t sB = sa + ASTAGE_BYTES;

#pragma unroll
        for (int ks = 0; ks < BK / 16; ks++) {
            uint32_t af[4][4], bf[4][2];
#pragma unroll
            for (int mt = 0; mt < 4; mt++) {
                int c = 2 * ks + a_chunk_hi;
                ldsm_x4(af[mt], sa + a_lane_row + mt * 2048 +
                                (uint32_t)((c ^ sw) << 4));
            }
#pragma unroll
            for (int nt = 0; nt < 4; nt++) {
                int c = 2 * ks + b_chunk_hi;
                ldsm_x2(bf[nt], sB + b_lane_row + nt * 1024 +
                                (uint32_t)((c ^ sw) << 4));
            }
#pragma unroll
            for (int mt = 0; mt < 4; mt++)
#pragma unroll
                for (int nt = 0; nt < 4; nt++)
                    mma16816(acc[mt][nt], af[mt], bf[nt]);
        }
    }

    // ---- epilogue: fused dequant (scale/bias per output channel) ----
    const int m_base = m0 + wm0 + (l >> 2);
    const int n_base = n0 + wn0 + (l & 3) * 2;
#pragma unroll
    for (int nt = 0; nt < 4; nt++) {
        const int n = n_base + nt * 8;
        const float s0 = __ldg(scales + n), s1 = __ldg(scales + n + 1);
        const float b0 = __ldg(bias + n), b1 = __ldg(bias + n + 1);
#pragma unroll
        for (int mt = 0; mt < 4; mt++) {
            const int r0 = m_base + mt * 16;
            float2 v0 = make_float2(acc[mt][nt][0] * s0 + b0,
                                    acc[mt][nt][1] * s1 + b1);
            float2 v1 = make_float2(acc[mt][nt][2] * s0 + b0,
                                    acc[mt][nt][3] * s1 + b1);
            *(float2*)(out + (size_t)r0 * D_OUT + n) = v0;
            *(float2*)(out + (size_t)(r0 + 8) * D_OUT + n) = v1;
        }
    }
}

// ============================================================================
// Host launch
// ============================================================================
extern "C" void kernel_launch(void* const* d_in, const int* in_sizes, int n_in,
                              void* d_out, int out_size) {
    const float* x = (const float*)d_in[0];
    const int* wq = (const int*)d_in[1];
    const float* scales = (const float*)d_in[2];
    const float* bias = (const float*)d_in[3];
    float* out = (float*)d_out;

    void *xh = nullptr, *wh = nullptr;
    cudaGetSymbolAddress(&xh, g_xh);
    cudaGetSymbolAddress(&wh, g_wh);

    // Stage 1: dtype conversions (x: fp32->fp16, w: int32->fp16 exact)
    {
        int n4x = (TOKENS * D_IN) / 4;
        cvt_x_kernel<<<n4x / 256, 256>>>((const float4*)x, (__half2*)xh, n4x);
        int n4w = (D_OUT * D_IN) / 4;
        cvt_w_kernel<<<n4w / 256, 256>>>((const int4*)wq, (__half2*)wh, n4w);
    }

    // Stage 2: pipelined HMMA GEMM + fused dequant epilogue
    static bool attr_set = false;
    if (!attr_set) {
        cudaFuncSetAttribute(gemm_kernel,
                             cudaFuncAttributeMaxDynamicSharedMemorySize,
                             SMEM_TOTAL);
        attr_set = true;
    }
    dim3 grid(D_OUT / BN, TOKENS / BM);   // (32, 64)
    gemm_kernel<<<grid, 256, SMEM_TOTAL>>>((const __half*)xh, (const __half*)wh,
                                           scales, bias, out);
}